// round 1
// baseline (speedup 1.0000x reference)
#include <cuda_runtime.h>
#include <math.h>

#define HH 1024
#define WW 1024
#define NPIX (HH * WW)
#define N_ITERS 100

// ---------------- device scratch (statically allocated, ~60 MB) ----------------
__device__ float  g_w[8][NPIX];     // propagation weights, planar
__device__ float2 g_b[NPIX];        // source term (IQ at colored pixels, else 0)
__device__ float  g_Y[NPIX];        // luminance plane
__device__ unsigned char g_mask[NPIX];  // isColored
__device__ float2 g_x0[NPIX];       // ping
__device__ float2 g_x1[NPIX];       // pong

// offsets in reference order: (-1,-1)(-1,0)(-1,1)(0,-1)(0,1)(1,-1)(1,0)(1,1)
__constant__ int c_di[8] = {-1,-1,-1, 0, 0, 1, 1, 1};
__constant__ int c_dj[8] = {-1, 0, 1,-1, 1,-1, 0, 1};

// ---------------- setup: Y, IQ, isColored, b, x0 init ----------------
__global__ void setup_kernel(const float* __restrict__ gray,
                             const float* __restrict__ app) {
    int pix = blockIdx.x * blockDim.x + threadIdx.x;
    if (pix >= NPIX) return;
    float g0 = gray[3*pix+0], g1 = gray[3*pix+1], g2 = gray[3*pix+2];
    float a0 = app [3*pix+0], a1 = app [3*pix+1], a2 = app [3*pix+2];

    const float inv255 = 1.0f / 255.0f;
    float diff = (fabsf(g0-a0) + fabsf(g1-a1) + fabsf(g2-a2)) * inv255;
    bool colored = diff > 0.01f;

    // gray luminance (rgb/255 dot [0.3,0.59,0.11])
    float Y = (0.3f*g0 + 0.59f*g1 + 0.11f*g2) * inv255;

    // appendix YIQ
    float ya = (0.3f*a0 + 0.59f*a1 + 0.11f*a2) * inv255;
    float r  = a0 * inv255;
    float bl = a2 * inv255;
    float I = 0.74f*(r - ya) - 0.27f*(bl - ya);
    float Q = 0.48f*(r - ya) + 0.41f*(bl - ya);

    float2 b = colored ? make_float2(I, Q) : make_float2(0.0f, 0.0f);

    g_Y[pix]   = Y;
    g_b[pix]   = b;
    g_x0[pix]  = b;          // scan carry initialized to b
    g_mask[pix] = colored ? 1 : 0;
}

// ---------------- weights: per-pixel 8-neighbor affinity ----------------
__global__ void weights_kernel() {
    int pix = blockIdx.x * blockDim.x + threadIdx.x;
    if (pix >= NPIX) return;
    int i = pix / WW, j = pix % WW;

    float Y = g_Y[pix];
    float nbr[8], valid[8];
    #pragma unroll
    for (int k = 0; k < 8; k++) {
        int ii = i + c_di[k], jj = j + c_dj[k];
        bool in = (ii >= 0) & (ii < HH) & (jj >= 0) & (jj < WW);
        valid[k] = in ? 1.0f : 0.0f;
        nbr[k]   = in ? g_Y[ii*WW + jj] : 0.0f;
    }

    float count = 1.0f, s = Y;
    #pragma unroll
    for (int k = 0; k < 8; k++) { count += valid[k]; s += nbr[k] * valid[k]; }
    float mean = s / count;

    float var = (Y - mean) * (Y - mean);
    #pragma unroll
    for (int k = 0; k < 8; k++) {
        float d = nbr[k] - mean;
        var += d * d * valid[k];
    }
    var /= count;
    float vs = fmaxf(0.6f * var, 2e-6f);
    float inv_vs = 1.0f / vs;

    float w[8], wsum = 0.0f;
    #pragma unroll
    for (int k = 0; k < 8; k++) {
        float d = nbr[k] - Y;
        w[k] = expf(-d * d * inv_vs) * valid[k];
        wsum += w[k];
    }
    float scale = (g_mask[pix] ? 0.0f : 1.0f) / wsum;
    #pragma unroll
    for (int k = 0; k < 8; k++) g_w[k][pix] = w[k] * scale;
}

// ---------------- main stencil iteration ----------------
__global__ void __launch_bounds__(256)
iter_kernel(int src_is_x0) {
    int j = blockIdx.x * 32 + threadIdx.x;
    int i = blockIdx.y * 8  + threadIdx.y;
    int pix = i * WW + j;

    const float2* __restrict__ xin = src_is_x0 ? g_x0 : g_x1;
    float2*       __restrict__ xout = src_is_x0 ? g_x1 : g_x0;

    // clamped indices: border weights are exactly 0 (valid-mask folded into w),
    // so clamped reads contribute nothing.
    int im = (i > 0)      ? i - 1 : 0;
    int ip = (i < HH - 1) ? i + 1 : HH - 1;
    int jm = (j > 0)      ? j - 1 : 0;
    int jp = (j < WW - 1) ? j + 1 : WW - 1;

    const float2* rm = xin + im * WW;
    const float2* r0 = xin + i  * WW;
    const float2* rp = xin + ip * WW;

    float w0 = g_w[0][pix], w1 = g_w[1][pix], w2 = g_w[2][pix], w3 = g_w[3][pix];
    float w4 = g_w[4][pix], w5 = g_w[5][pix], w6 = g_w[6][pix], w7 = g_w[7][pix];

    float2 acc = g_b[pix];
    float2 t;
    t = rm[jm]; acc.x = fmaf(w0, t.x, acc.x); acc.y = fmaf(w0, t.y, acc.y);
    t = rm[j ]; acc.x = fmaf(w1, t.x, acc.x); acc.y = fmaf(w1, t.y, acc.y);
    t = rm[jp]; acc.x = fmaf(w2, t.x, acc.x); acc.y = fmaf(w2, t.y, acc.y);
    t = r0[jm]; acc.x = fmaf(w3, t.x, acc.x); acc.y = fmaf(w3, t.y, acc.y);
    t = r0[jp]; acc.x = fmaf(w4, t.x, acc.x); acc.y = fmaf(w4, t.y, acc.y);
    t = rp[jm]; acc.x = fmaf(w5, t.x, acc.x); acc.y = fmaf(w5, t.y, acc.y);
    t = rp[j ]; acc.x = fmaf(w6, t.x, acc.x); acc.y = fmaf(w6, t.y, acc.y);
    t = rp[jp]; acc.x = fmaf(w7, t.x, acc.x); acc.y = fmaf(w7, t.y, acc.y);

    xout[pix] = acc;
}

// ---------------- finalize: YIQ -> RGB ----------------
__global__ void final_kernel(float* __restrict__ out, int src_is_x0) {
    int pix = blockIdx.x * blockDim.x + threadIdx.x;
    if (pix >= NPIX) return;
    const float2* __restrict__ x = src_is_x0 ? g_x0 : g_x1;
    float y = g_Y[pix];
    float I = x[pix].x, Q = x[pix].y;

    float r = y + 0.9468822170900693f  * I + 0.6235565819861433f * Q;
    float g = y - 0.27478764629897834f * I - 0.6356910791873801f * Q;
    float b = y - 1.1085450346420322f  * I + 1.7090069284064666f * Q;

    out[3*pix+0] = fminf(fmaxf(r, 0.0f), 1.0f) * 255.0f;
    out[3*pix+1] = fminf(fmaxf(g, 0.0f), 1.0f) * 255.0f;
    out[3*pix+2] = fminf(fmaxf(b, 0.0f), 1.0f) * 255.0f;
}

extern "C" void kernel_launch(void* const* d_in, const int* in_sizes, int n_in,
                              void* d_out, int out_size) {
    const float* gray = (const float*)d_in[0];
    const float* app  = (const float*)d_in[1];
    float* out = (float*)d_out;

    int threads = 256;
    int blocks1d = (NPIX + threads - 1) / threads;

    setup_kernel<<<blocks1d, threads>>>(gray, app);
    weights_kernel<<<blocks1d, threads>>>();

    dim3 blk(32, 8);
    dim3 grd(WW / 32, HH / 8);
    int src_is_x0 = 1;
    for (int it = 0; it < N_ITERS; it++) {
        iter_kernel<<<grd, blk>>>(src_is_x0);
        src_is_x0 ^= 1;
    }
    // N_ITERS=100 (even): final result is back in g_x0 (src_is_x0 == 1)
    final_kernel<<<blocks1d, threads>>>(out, src_is_x0);
}